// round 2
// baseline (speedup 1.0000x reference)
#include <cuda_runtime.h>
#include <math.h>

// Shapes
#define Bsz 8
#define Cch 32
#define Hh  256
#define Ww  256
#define IMG 256   // Bsz*Cch
#define NK1 64    // rows kept: k1 in [0,32) U [224,256)
#define NK2 32    // cols kept: k2 in [0,32)
#define KK  64    // 2*NK2 (interleaved re/im)

// Scratch (static device globals; no allocations allowed)
__device__ float gZ [IMG*Hh*KK];     // F1 out: [img][h][2*k2]
__device__ float gY [IMG*NK1*KK];    // F2 out: [img][k1i][2*k2]
__device__ float gF [IMG*NK1*KK];    // mix out
__device__ float gT [IMG*KK*Hh];     // I1 out: [img][kk][h]  (transposed for coalesced I2)
__device__ float gW1[Ww*KK];         // F1 weights [w][2*k2]
__device__ float gE2[Hh*NK1*2];      // F2 weights [h][k1i] complex, /256
__device__ float gEI[NK1*Hh*2];      // I1 weights [k1i][h] complex, /16
__device__ float gWB[KK*Ww];         // I2 weights [kk][w]
__device__ float gKCP[2*32*32*32*2]; // kernel^r
__device__ float gG  [2*32*32*32*2]; // circulant taps [s][d][m1][m2] complex

// ---------------- weight tables ----------------
__global__ void k_tables() {
    int tid = blockIdx.x * 256 + threadIdx.x;  // 0..16383
    const float W0 = 6.2831853071795864769f / 256.0f;
    if (tid < 8192) {  // W1: 256 w x 32 k2
        int w = tid >> 5, k2 = tid & 31;
        int a = (k2 * w) & 255;
        float s, c; sincosf(a * W0, &s, &c);
        gW1[w * KK + 2 * k2]     = c;
        gW1[w * KK + 2 * k2 + 1] = -s;
    }
    {   // E2 / EI: 256 h x 64 k1i
        int h = tid >> 6, k1i = tid & 63;
        int k1 = (k1i < 32) ? k1i : (192 + k1i);
        int a = (k1 * h) & 255;
        float s, c; sincosf(a * W0, &s, &c);
        gE2[(h * NK1 + k1i) * 2]     =  c * (1.0f / 256.0f);
        gE2[(h * NK1 + k1i) * 2 + 1] = -s * (1.0f / 256.0f);
        gEI[(k1i * Hh + h) * 2]      =  c * (1.0f / 16.0f);
        gEI[(k1i * Hh + h) * 2 + 1]  =  s * (1.0f / 16.0f);
    }
    {   // WB: 64 kk x 256 w
        int kk = tid >> 8, w = tid & 255;
        int k2 = kk >> 1;
        int a = (k2 * w) & 255;
        float s, c; sincosf(a * W0, &s, &c);
        float v;
        if ((kk & 1) == 0) v = (k2 == 0 ? 1.0f : 2.0f) * (1.0f / 16.0f) * c;
        else               v = (k2 == 0 ? 0.0f : -(2.0f / 16.0f) * s);
        gWB[kk * Ww + w] = v;
    }
}

// ---------------- kernel^r (elementwise complex pow) ----------------
__global__ void k_pow(const float* __restrict__ kern, const float* __restrict__ rp) {
    int idx = blockIdx.x * 256 + threadIdx.x;  // 65536
    float kr = kern[2 * idx], ki = kern[2 * idx + 1];
    float r = *rp;
    float outr, outi;
    if (r == 1.0f) { outr = kr; outi = ki; }
    else {
        float m2 = kr * kr + ki * ki;
        if (m2 == 0.0f) { outr = 0.0f; outi = 0.0f; }
        else {
            float mag = expf(0.5f * r * logf(m2));
            float th = atan2f(ki, kr) * r;
            float s, c; sincosf(th, &s, &c);
            outr = mag * c; outi = mag * s;
        }
    }
    gKCP[2 * idx] = outr; gKCP[2 * idx + 1] = outi;
}

// ---------------- circulant taps G = (1/32) * ifft_j(kcp) ----------------
__global__ void k_g() {
    __shared__ float tw[64];
    int tid = threadIdx.x;  // 256
    if (tid < 32) {
        float s, c; sincosf(tid * (6.2831853071795864769f / 32.0f), &s, &c);
        tw[2 * tid] = c; tw[2 * tid + 1] = s;
    }
    __syncthreads();
    int bi = blockIdx.x;           // 256
    int s_ = bi >> 7;
    int rest = bi & 127;
    int m1 = rest >> 2, dq = rest & 3;
    int d = dq * 8 + (tid >> 5);
    int m2 = tid & 31;
    float ar = 0.0f, ai = 0.0f;
    #pragma unroll 8
    for (int j = 0; j < 32; j++) {
        int a = (j * d) & 31;
        float tr = tw[2 * a], ti = tw[2 * a + 1];
        int base = (((s_ * 32 + j) * 32 + m1) * 32 + m2) * 2;
        float cr = gKCP[base], ci = gKCP[base + 1];
        ar += tr * cr - ti * ci;
        ai += tr * ci + ti * cr;
    }
    int ob = (((s_ * 32 + d) * 32 + m1) * 32 + m2) * 2;
    gG[ob]     = ar * (1.0f / 32.0f);
    gG[ob + 1] = ai * (1.0f / 32.0f);
}

// ---------------- F1: Z[row][kk] = sum_w x[row][w] * W1[w][kk] ----------------
__global__ void k_f1(const float* __restrict__ x) {
    __shared__ float Xs[64][68];
    __shared__ float Ws[64][68];
    int tid = threadIdx.x;      // 128
    int r0 = blockIdx.x * 64;   // 1024 blocks
    int ty = tid >> 3;          // 0..15 -> 4 rows each
    int tx = tid & 7;           // 0..7  -> 8 cols each
    float acc[4][8];
    #pragma unroll
    for (int i = 0; i < 4; i++)
        #pragma unroll
        for (int j = 0; j < 8; j++) acc[i][j] = 0.0f;

    for (int kt = 0; kt < 4; kt++) {
        #pragma unroll
        for (int t = 0; t < 32; t++) {
            int lin = tid + t * 128;
            int row = lin >> 6, col = lin & 63;
            Xs[row][col] = x[(r0 + row) * 256 + kt * 64 + col];
            Ws[row][col] = gW1[(kt * 64 + row) * KK + col];
        }
        __syncthreads();
        #pragma unroll 4
        for (int k = 0; k < 64; k++) {
            float xa[4], wv[8];
            #pragma unroll
            for (int i = 0; i < 4; i++) xa[i] = Xs[ty * 4 + i][k];
            #pragma unroll
            for (int j = 0; j < 8; j++) wv[j] = Ws[k][tx * 8 + j];
            #pragma unroll
            for (int i = 0; i < 4; i++)
                #pragma unroll
                for (int j = 0; j < 8; j++) acc[i][j] += xa[i] * wv[j];
        }
        __syncthreads();
    }
    #pragma unroll
    for (int i = 0; i < 4; i++)
        #pragma unroll
        for (int j = 0; j < 8; j++)
            gZ[(r0 + ty * 4 + i) * KK + tx * 8 + j] = acc[i][j];
}

// ---------------- F2: Y[img][k1i][k2] = sum_h E2[h][k1i] * Z[img][h][k2] ----------------
__global__ void k_f2() {
    __shared__ float Zs[128][64];
    int tid = threadIdx.x;      // 256
    int img = blockIdx.x;       // 256
    int k1i = tid >> 2;
    int g = tid & 3;            // 8 k2 each
    float accr[8], acci[8];
    #pragma unroll
    for (int q = 0; q < 8; q++) { accr[q] = 0.0f; acci[q] = 0.0f; }
    const float* Zimg = gZ + img * Hh * KK;
    for (int half = 0; half < 2; half++) {
        __syncthreads();
        #pragma unroll
        for (int t = 0; t < 32; t++) {
            int lin = tid + t * 256;
            int row = lin >> 6, col = lin & 63;
            Zs[row][col] = Zimg[(half * 128 + row) * KK + col];
        }
        __syncthreads();
        for (int hh = 0; hh < 128; hh++) {
            int h = half * 128 + hh;
            float2 e = *(const float2*)&gE2[(h * NK1 + k1i) * 2];
            const float* zrow = &Zs[hh][g * 16];
            float4 z0 = *(const float4*)&zrow[0];
            float4 z1 = *(const float4*)&zrow[4];
            float4 z2 = *(const float4*)&zrow[8];
            float4 z3 = *(const float4*)&zrow[12];
            float zr[8] = {z0.x, z0.z, z1.x, z1.z, z2.x, z2.z, z3.x, z3.z};
            float zi[8] = {z0.y, z0.w, z1.y, z1.w, z2.y, z2.w, z3.y, z3.w};
            #pragma unroll
            for (int q = 0; q < 8; q++) {
                accr[q] += e.x * zr[q] - e.y * zi[q];
                acci[q] += e.x * zi[q] + e.y * zr[q];
            }
        }
    }
    float* out = gY + (img * NK1 + k1i) * KK + g * 16;
    #pragma unroll
    for (int q = 0; q < 8; q++) { out[2 * q] = accr[q]; out[2 * q + 1] = acci[q]; }
}

// ---------------- Mix: F[b][o][k1i][k2] = sum_c G[s][(o-c)%32][m1][k2] * Y[b][c][k1i][k2] ----------------
__global__ void k_mix() {
    __shared__ float Ys[8][32][16];        // [b][c][2*kq]
    __shared__ float Gr[32][9], Gi[32][9]; // padded
    int tid = threadIdx.x;   // 256
    int bi = blockIdx.x;     // 256: (k1i, k2-quad)
    int k1i = bi >> 2, q = bi & 3;
    int s_ = (k1i < 32) ? 0 : 1;
    int m1 = k1i & 31;
    int b = tid >> 5, c = tid & 31;
    {
        const float4* ysrc = (const float4*)(gY + ((b * 32 + c) * NK1 + k1i) * KK + q * 16);
        float4* dst = (float4*)&Ys[b][c][0];
        #pragma unroll
        for (int t = 0; t < 4; t++) dst[t] = ysrc[t];
    }
    {
        int d = tid >> 3, kq = tid & 7;
        int m2 = q * 8 + kq;
        int gi = (((s_ * 32 + d) * 32 + m1) * 32 + m2) * 2;
        Gr[d][kq] = gG[gi]; Gi[d][kq] = gG[gi + 1];
    }
    __syncthreads();
    int o = c;
    float ar[8] = {0, 0, 0, 0, 0, 0, 0, 0}, ai[8] = {0, 0, 0, 0, 0, 0, 0, 0};
    for (int cc = 0; cc < 32; cc++) {
        int d = (o - cc) & 31;
        #pragma unroll
        for (int kq = 0; kq < 8; kq++) {
            float gr = Gr[d][kq], gim = Gi[d][kq];
            float yr = Ys[b][cc][2 * kq], yi = Ys[b][cc][2 * kq + 1];
            ar[kq] += gr * yr - gim * yi;
            ai[kq] += gr * yi + gim * yr;
        }
    }
    float* fo = gF + ((b * 32 + o) * NK1 + k1i) * KK + q * 16;
    #pragma unroll
    for (int kq = 0; kq < 8; kq++) { fo[2 * kq] = ar[kq]; fo[2 * kq + 1] = ai[kq]; }
}

// ---------------- I1: T[img][kk][h] = sum_k1 EI[k1i][h] * F[img][k1i][k2] ----------------
__global__ void k_i1() {
    __shared__ float Fs[NK1][KK];  // 16KB
    int tid = threadIdx.x;  // 256 = h
    int img = blockIdx.x;   // 256
    const float* fimg = gF + img * NK1 * KK;
    #pragma unroll
    for (int t = 0; t < 16; t++) {
        int lin = tid + t * 256;
        ((float*)Fs)[lin] = fimg[lin];
    }
    __syncthreads();
    float tr[32], ti[32];
    #pragma unroll
    for (int k2 = 0; k2 < 32; k2++) { tr[k2] = 0.0f; ti[k2] = 0.0f; }
    int h = tid;
    for (int k1i = 0; k1i < 64; k1i++) {
        float2 e = *(const float2*)&gEI[(k1i * Hh + h) * 2];
        #pragma unroll
        for (int k2 = 0; k2 < 32; k2++) {
            float fr = Fs[k1i][2 * k2], fi = Fs[k1i][2 * k2 + 1];
            tr[k2] += e.x * fr - e.y * fi;
            ti[k2] += e.x * fi + e.y * fr;
        }
    }
    float* tout = gT + img * KK * Hh;
    #pragma unroll
    for (int k2 = 0; k2 < 32; k2++) {
        tout[(2 * k2) * Hh + h]     = tr[k2];
        tout[(2 * k2 + 1) * Hh + h] = ti[k2];
    }
}

// ---------------- I2: y[img][h][w] = sum_kk T[img][kk][h] * WB[kk][w] ----------------
__global__ void k_i2(float* __restrict__ out) {
    __shared__ float Ts[64][68];
    __shared__ float Wb[64][68];
    int tid = threadIdx.x;  // 128
    int bi = blockIdx.x;    // 256*4*4 = 4096
    int img = bi >> 4;
    int hb = (bi >> 2) & 3;
    int wb = bi & 3;
    int h0 = hb * 64, w0 = wb * 64;
    #pragma unroll
    for (int t = 0; t < 32; t++) {
        int lin = tid + t * 128;
        int row = lin >> 6, col = lin & 63;
        Ts[row][col] = gT[(img * KK + row) * Hh + h0 + col];
        Wb[row][col] = gWB[row * Ww + w0 + col];
    }
    __syncthreads();
    int ty = tid >> 3, tx = tid & 7;
    float acc[4][8];
    #pragma unroll
    for (int i = 0; i < 4; i++)
        #pragma unroll
        for (int j = 0; j < 8; j++) acc[i][j] = 0.0f;
    #pragma unroll 4
    for (int k = 0; k < 64; k++) {
        float ta[4], wv[8];
        #pragma unroll
        for (int i = 0; i < 4; i++) ta[i] = Ts[k][ty * 4 + i];
        #pragma unroll
        for (int j = 0; j < 8; j++) wv[j] = Wb[k][tx * 8 + j];
        #pragma unroll
        for (int i = 0; i < 4; i++)
            #pragma unroll
            for (int j = 0; j < 8; j++) acc[i][j] += ta[i] * wv[j];
    }
    #pragma unroll
    for (int i = 0; i < 4; i++)
        #pragma unroll
        for (int j = 0; j < 8; j++)
            out[(img * Hh + h0 + ty * 4 + i) * Ww + w0 + tx * 8 + j] = acc[i][j];
}

extern "C" void kernel_launch(void* const* d_in, const int* in_sizes, int n_in,
                              void* d_out, int out_size) {
    const float* x    = (const float*)d_in[0];
    const float* kern = (const float*)d_in[1];
    const float* r    = (const float*)d_in[2];
    float* out = (float*)d_out;

    k_tables<<<64, 256>>>();
    k_pow<<<256, 256>>>(kern, r);
    k_g<<<256, 256>>>();
    k_f1<<<1024, 128>>>(x);
    k_f2<<<256, 256>>>();
    k_mix<<<256, 256>>>();
    k_i1<<<256, 256>>>();
    k_i2<<<4096, 128>>>(out);
}

// round 3
// speedup vs baseline: 1.0002x; 1.0002x over previous
#include <cuda_runtime.h>
#include <math.h>

// Shapes
#define Bsz 8
#define Cch 32
#define Hh  256
#define Ww  256
#define IMG 256   // Bsz*Cch
#define NK1 64    // rows kept: k1 in [0,32) U [224,256)
#define NK2 32    // cols kept: k2 in [0,32)
#define KK  64    // 2*NK2 (interleaved re/im)

// Scratch (static device globals; no allocations allowed)
__device__ float gZ [IMG*Hh*KK];     // F1 out: [img][h][2*k2]
__device__ float gY [IMG*NK1*KK];    // F2 out: [img][k1i][2*k2]
__device__ float gF [IMG*NK1*KK];    // mix out
__device__ float gT [IMG*KK*Hh];     // I1 out: [img][kk][h]  (transposed for coalesced I2)
__device__ float gW1[Ww*KK];         // F1 weights [w][2*k2]
__device__ float gE2[Hh*NK1*2];      // F2 weights [h][k1i] complex, /256
__device__ float gEI[NK1*Hh*2];      // I1 weights [k1i][h] complex, /16
__device__ float gWB[KK*Ww];         // I2 weights [kk][w]
__device__ float gKCP[2*32*32*32*2]; // kernel^r
__device__ float gG  [2*32*32*32*2]; // circulant taps [s][d][m1][m2] complex

// ---------------- weight tables ----------------
__global__ void k_tables() {
    int tid = blockIdx.x * 256 + threadIdx.x;  // 0..16383
    const float W0 = 6.2831853071795864769f / 256.0f;
    if (tid < 8192) {  // W1: 256 w x 32 k2
        int w = tid >> 5, k2 = tid & 31;
        int a = (k2 * w) & 255;
        float s, c; sincosf(a * W0, &s, &c);
        gW1[w * KK + 2 * k2]     = c;
        gW1[w * KK + 2 * k2 + 1] = -s;
    }
    {   // E2 / EI: 256 h x 64 k1i
        int h = tid >> 6, k1i = tid & 63;
        int k1 = (k1i < 32) ? k1i : (192 + k1i);
        int a = (k1 * h) & 255;
        float s, c; sincosf(a * W0, &s, &c);
        gE2[(h * NK1 + k1i) * 2]     =  c * (1.0f / 256.0f);
        gE2[(h * NK1 + k1i) * 2 + 1] = -s * (1.0f / 256.0f);
        gEI[(k1i * Hh + h) * 2]      =  c * (1.0f / 16.0f);
        gEI[(k1i * Hh + h) * 2 + 1]  =  s * (1.0f / 16.0f);
    }
    {   // WB: 64 kk x 256 w
        int kk = tid >> 8, w = tid & 255;
        int k2 = kk >> 1;
        int a = (k2 * w) & 255;
        float s, c; sincosf(a * W0, &s, &c);
        float v;
        if ((kk & 1) == 0) v = (k2 == 0 ? 1.0f : 2.0f) * (1.0f / 16.0f) * c;
        else               v = (k2 == 0 ? 0.0f : -(2.0f / 16.0f) * s);
        gWB[kk * Ww + w] = v;
    }
}

// ---------------- kernel^r (elementwise complex pow) ----------------
__global__ void k_pow(const float* __restrict__ kern, const float* __restrict__ rp) {
    int idx = blockIdx.x * 256 + threadIdx.x;  // 65536
    float kr = kern[2 * idx], ki = kern[2 * idx + 1];
    float r = *rp;
    float outr, outi;
    if (r == 1.0f) { outr = kr; outi = ki; }
    else {
        float m2 = kr * kr + ki * ki;
        if (m2 == 0.0f) { outr = 0.0f; outi = 0.0f; }
        else {
            float mag = expf(0.5f * r * logf(m2));
            float th = atan2f(ki, kr) * r;
            float s, c; sincosf(th, &s, &c);
            outr = mag * c; outi = mag * s;
        }
    }
    gKCP[2 * idx] = outr; gKCP[2 * idx + 1] = outi;
}

// ---------------- circulant taps G = (1/32) * ifft_j(kcp) ----------------
__global__ void k_g() {
    __shared__ float tw[64];
    int tid = threadIdx.x;  // 256
    if (tid < 32) {
        float s, c; sincosf(tid * (6.2831853071795864769f / 32.0f), &s, &c);
        tw[2 * tid] = c; tw[2 * tid + 1] = s;
    }
    __syncthreads();
    int bi = blockIdx.x;           // 256
    int s_ = bi >> 7;
    int rest = bi & 127;
    int m1 = rest >> 2, dq = rest & 3;
    int d = dq * 8 + (tid >> 5);
    int m2 = tid & 31;
    float ar = 0.0f, ai = 0.0f;
    #pragma unroll 8
    for (int j = 0; j < 32; j++) {
        int a = (j * d) & 31;
        float tr = tw[2 * a], ti = tw[2 * a + 1];
        int base = (((s_ * 32 + j) * 32 + m1) * 32 + m2) * 2;
        float cr = gKCP[base], ci = gKCP[base + 1];
        ar += tr * cr - ti * ci;
        ai += tr * ci + ti * cr;
    }
    int ob = (((s_ * 32 + d) * 32 + m1) * 32 + m2) * 2;
    gG[ob]     = ar * (1.0f / 32.0f);
    gG[ob + 1] = ai * (1.0f / 32.0f);
}

// ---------------- F1: Z[row][kk] = sum_w x[row][w] * W1[w][kk] ----------------
__global__ void k_f1(const float* __restrict__ x) {
    __shared__ float Xs[64][68];
    __shared__ float Ws[64][68];
    int tid = threadIdx.x;      // 128
    int r0 = blockIdx.x * 64;   // 1024 blocks
    int ty = tid >> 3;          // 0..15 -> 4 rows each
    int tx = tid & 7;           // 0..7  -> 8 cols each
    float acc[4][8];
    #pragma unroll
    for (int i = 0; i < 4; i++)
        #pragma unroll
        for (int j = 0; j < 8; j++) acc[i][j] = 0.0f;

    for (int kt = 0; kt < 4; kt++) {
        #pragma unroll
        for (int t = 0; t < 32; t++) {
            int lin = tid + t * 128;
            int row = lin >> 6, col = lin & 63;
            Xs[row][col] = x[(r0 + row) * 256 + kt * 64 + col];
            Ws[row][col] = gW1[(kt * 64 + row) * KK + col];
        }
        __syncthreads();
        #pragma unroll 4
        for (int k = 0; k < 64; k++) {
            float xa[4], wv[8];
            #pragma unroll
            for (int i = 0; i < 4; i++) xa[i] = Xs[ty * 4 + i][k];
            #pragma unroll
            for (int j = 0; j < 8; j++) wv[j] = Ws[k][tx * 8 + j];
            #pragma unroll
            for (int i = 0; i < 4; i++)
                #pragma unroll
                for (int j = 0; j < 8; j++) acc[i][j] += xa[i] * wv[j];
        }
        __syncthreads();
    }
    #pragma unroll
    for (int i = 0; i < 4; i++)
        #pragma unroll
        for (int j = 0; j < 8; j++)
            gZ[(r0 + ty * 4 + i) * KK + tx * 8 + j] = acc[i][j];
}

// ---------------- F2: Y[img][k1i][k2] = sum_h E2[h][k1i] * Z[img][h][k2] ----------------
__global__ void k_f2() {
    __shared__ float Zs[128][64];
    int tid = threadIdx.x;      // 256
    int img = blockIdx.x;       // 256
    int k1i = tid >> 2;
    int g = tid & 3;            // 8 k2 each
    float accr[8], acci[8];
    #pragma unroll
    for (int q = 0; q < 8; q++) { accr[q] = 0.0f; acci[q] = 0.0f; }
    const float* Zimg = gZ + img * Hh * KK;
    for (int half = 0; half < 2; half++) {
        __syncthreads();
        #pragma unroll
        for (int t = 0; t < 32; t++) {
            int lin = tid + t * 256;
            int row = lin >> 6, col = lin & 63;
            Zs[row][col] = Zimg[(half * 128 + row) * KK + col];
        }
        __syncthreads();
        for (int hh = 0; hh < 128; hh++) {
            int h = half * 128 + hh;
            float2 e = *(const float2*)&gE2[(h * NK1 + k1i) * 2];
            const float* zrow = &Zs[hh][g * 16];
            float4 z0 = *(const float4*)&zrow[0];
            float4 z1 = *(const float4*)&zrow[4];
            float4 z2 = *(const float4*)&zrow[8];
            float4 z3 = *(const float4*)&zrow[12];
            float zr[8] = {z0.x, z0.z, z1.x, z1.z, z2.x, z2.z, z3.x, z3.z};
            float zi[8] = {z0.y, z0.w, z1.y, z1.w, z2.y, z2.w, z3.y, z3.w};
            #pragma unroll
            for (int q = 0; q < 8; q++) {
                accr[q] += e.x * zr[q] - e.y * zi[q];
                acci[q] += e.x * zi[q] + e.y * zr[q];
            }
        }
    }
    float* out = gY + (img * NK1 + k1i) * KK + g * 16;
    #pragma unroll
    for (int q = 0; q < 8; q++) { out[2 * q] = accr[q]; out[2 * q + 1] = acci[q]; }
}

// ---------------- Mix: F[b][o][k1i][k2] = sum_c G[s][(o-c)%32][m1][k2] * Y[b][c][k1i][k2] ----------------
__global__ void k_mix() {
    __shared__ float Ys[8][32][16];        // [b][c][2*kq]
    __shared__ float Gr[32][9], Gi[32][9]; // padded
    int tid = threadIdx.x;   // 256
    int bi = blockIdx.x;     // 256: (k1i, k2-quad)
    int k1i = bi >> 2, q = bi & 3;
    int s_ = (k1i < 32) ? 0 : 1;
    int m1 = k1i & 31;
    int b = tid >> 5, c = tid & 31;
    {
        const float4* ysrc = (const float4*)(gY + ((b * 32 + c) * NK1 + k1i) * KK + q * 16);
        float4* dst = (float4*)&Ys[b][c][0];
        #pragma unroll
        for (int t = 0; t < 4; t++) dst[t] = ysrc[t];
    }
    {
        int d = tid >> 3, kq = tid & 7;
        int m2 = q * 8 + kq;
        int gi = (((s_ * 32 + d) * 32 + m1) * 32 + m2) * 2;
        Gr[d][kq] = gG[gi]; Gi[d][kq] = gG[gi + 1];
    }
    __syncthreads();
    int o = c;
    float ar[8] = {0, 0, 0, 0, 0, 0, 0, 0}, ai[8] = {0, 0, 0, 0, 0, 0, 0, 0};
    for (int cc = 0; cc < 32; cc++) {
        int d = (o - cc) & 31;
        #pragma unroll
        for (int kq = 0; kq < 8; kq++) {
            float gr = Gr[d][kq], gim = Gi[d][kq];
            float yr = Ys[b][cc][2 * kq], yi = Ys[b][cc][2 * kq + 1];
            ar[kq] += gr * yr - gim * yi;
            ai[kq] += gr * yi + gim * yr;
        }
    }
    float* fo = gF + ((b * 32 + o) * NK1 + k1i) * KK + q * 16;
    #pragma unroll
    for (int kq = 0; kq < 8; kq++) { fo[2 * kq] = ar[kq]; fo[2 * kq + 1] = ai[kq]; }
}

// ---------------- I1: T[img][kk][h] = sum_k1 EI[k1i][h] * F[img][k1i][k2] ----------------
__global__ void k_i1() {
    __shared__ float Fs[NK1][KK];  // 16KB
    int tid = threadIdx.x;  // 256 = h
    int img = blockIdx.x;   // 256
    const float* fimg = gF + img * NK1 * KK;
    #pragma unroll
    for (int t = 0; t < 16; t++) {
        int lin = tid + t * 256;
        ((float*)Fs)[lin] = fimg[lin];
    }
    __syncthreads();
    float tr[32], ti[32];
    #pragma unroll
    for (int k2 = 0; k2 < 32; k2++) { tr[k2] = 0.0f; ti[k2] = 0.0f; }
    int h = tid;
    for (int k1i = 0; k1i < 64; k1i++) {
        float2 e = *(const float2*)&gEI[(k1i * Hh + h) * 2];
        #pragma unroll
        for (int k2 = 0; k2 < 32; k2++) {
            float fr = Fs[k1i][2 * k2], fi = Fs[k1i][2 * k2 + 1];
            tr[k2] += e.x * fr - e.y * fi;
            ti[k2] += e.x * fi + e.y * fr;
        }
    }
    float* tout = gT + img * KK * Hh;
    #pragma unroll
    for (int k2 = 0; k2 < 32; k2++) {
        tout[(2 * k2) * Hh + h]     = tr[k2];
        tout[(2 * k2 + 1) * Hh + h] = ti[k2];
    }
}

// ---------------- I2: y[img][h][w] = sum_kk T[img][kk][h] * WB[kk][w] ----------------
__global__ void k_i2(float* __restrict__ out) {
    __shared__ float Ts[64][68];
    __shared__ float Wb[64][68];
    int tid = threadIdx.x;  // 128
    int bi = blockIdx.x;    // 256*4*4 = 4096
    int img = bi >> 4;
    int hb = (bi >> 2) & 3;
    int wb = bi & 3;
    int h0 = hb * 64, w0 = wb * 64;
    #pragma unroll
    for (int t = 0; t < 32; t++) {
        int lin = tid + t * 128;
        int row = lin >> 6, col = lin & 63;
        Ts[row][col] = gT[(img * KK + row) * Hh + h0 + col];
        Wb[row][col] = gWB[row * Ww + w0 + col];
    }
    __syncthreads();
    int ty = tid >> 3, tx = tid & 7;
    float acc[4][8];
    #pragma unroll
    for (int i = 0; i < 4; i++)
        #pragma unroll
        for (int j = 0; j < 8; j++) acc[i][j] = 0.0f;
    #pragma unroll 4
    for (int k = 0; k < 64; k++) {
        float ta[4], wv[8];
        #pragma unroll
        for (int i = 0; i < 4; i++) ta[i] = Ts[k][ty * 4 + i];
        #pragma unroll
        for (int j = 0; j < 8; j++) wv[j] = Wb[k][tx * 8 + j];
        #pragma unroll
        for (int i = 0; i < 4; i++)
            #pragma unroll
            for (int j = 0; j < 8; j++) acc[i][j] += ta[i] * wv[j];
    }
    #pragma unroll
    for (int i = 0; i < 4; i++)
        #pragma unroll
        for (int j = 0; j < 8; j++)
            out[(img * Hh + h0 + ty * 4 + i) * Ww + w0 + tx * 8 + j] = acc[i][j];
}

extern "C" void kernel_launch(void* const* d_in, const int* in_sizes, int n_in,
                              void* d_out, int out_size) {
    const float* x    = (const float*)d_in[0];
    const float* kern = (const float*)d_in[1];
    const float* r    = (const float*)d_in[2];
    float* out = (float*)d_out;

    k_tables<<<64, 256>>>();
    k_pow<<<256, 256>>>(kern, r);
    k_g<<<256, 256>>>();
    k_f1<<<1024, 128>>>(x);
    k_f2<<<256, 256>>>();
    k_mix<<<256, 256>>>();
    k_i1<<<256, 256>>>();
    k_i2<<<4096, 128>>>(out);
}

// round 4
// speedup vs baseline: 1.4862x; 1.4859x over previous
#include <cuda_runtime.h>
#include <math.h>

typedef unsigned long long ull;
#define IMG 256

__device__ float gZ [IMG*256*64];
__device__ float gY [IMG*64*64];
__device__ float gF [IMG*64*64];
__device__ float gT [IMG*256*64];
__device__ float gW1[128*64];
__device__ float gTb[256*68];
__device__ float gTA[256*69];
__device__ float gWB2[64*128];
__device__ float gKCP[2*32*32*32*2];
__device__ float gG  [2*32*32*32*2];

__device__ __forceinline__ ull pk(float x) {
    ull r; unsigned xi = __float_as_uint(x);
    asm("mov.b64 %0, {%1, %1};" : "=l"(r) : "r"(xi));
    return r;
}
__device__ __forceinline__ void fma2(ull& d, ull a, ull b) {
    asm("fma.rn.f32x2 %0, %1, %2, %0;" : "+l"(d) : "l"(a), "l"(b));
}
__device__ __forceinline__ float2 uf(ull v) {
    float2 f; asm("mov.b64 {%0, %1}, %2;" : "=f"(f.x), "=f"(f.y) : "l"(v));
    return f;
}
__device__ __forceinline__ int k2map(int p) { return (p < 16) ? 2 * p : 2 * (p - 16) + 1; }

__global__ void k_tables() {
    int idx = blockIdx.x * 256 + threadIdx.x;  // 69*256
    const float W0 = 6.2831853071795864769f / 256.0f;
    if (idx < 8192) {           // gW1 [w<128][c p-order]
        int w = idx >> 6, c = idx & 63;
        int k2 = k2map(c >> 1);
        float s, cc; sincosf(((k2 * w) & 255) * W0, &s, &cc);
        gW1[idx] = (c & 1) ? -s : cc;
    }
    if (idx < 256 * 68) {       // gTb [h][2t+s], t<=32
        int h = idx / 68, tr = idx % 68;
        int t = tr >> 1; float v = 0.f;
        if (t <= 32) { float s, cc; sincosf(((t * h) & 255) * W0, &s, &cc); v = (tr & 1) ? s : cc; }
        gTb[idx] = v;
    }
    if (idx < 256 * 69) {       // gTA [h][k<66] /16
        int h = idx / 69, tr = idx % 69;
        int t = tr >> 1; float v = 0.f;
        if (tr < 66) { float s, cc; sincosf(((t * h) & 255) * W0, &s, &cc); v = ((tr & 1) ? s : cc) * 0.0625f; }
        gTA[idx] = v;
    }
    if (idx < 8192) {           // gWB2 [kk p-order][w<128]
        int kk = idx >> 7, w = idx & 127;
        int k2 = k2map(kk >> 1);
        float s, cc; sincosf(((k2 * w) & 255) * W0, &s, &cc);
        float v;
        if ((kk & 1) == 0) v = ((k2 == 0) ? 1.0f : 2.0f) * 0.0625f * cc;
        else               v = (k2 == 0) ? 0.0f : -0.125f * s;
        gWB2[idx] = v;
    }
}

__global__ void k_pow(const float* __restrict__ kern, const float* __restrict__ rp) {
    int idx = blockIdx.x * 256 + threadIdx.x;
    float kr = kern[2 * idx], ki = kern[2 * idx + 1];
    float r = *rp, outr, outi;
    if (r == 1.0f) { outr = kr; outi = ki; }
    else {
        float m2 = kr * kr + ki * ki;
        if (m2 == 0.0f) { outr = 0.0f; outi = 0.0f; }
        else {
            float mag = expf(0.5f * r * logf(m2));
            float th = atan2f(ki, kr) * r;
            float s, c; sincosf(th, &s, &c);
            outr = mag * c; outi = mag * s;
        }
    }
    gKCP[2 * idx] = outr; gKCP[2 * idx + 1] = outi;
}

__global__ void k_g() {
    __shared__ float tw[64];
    int tid = threadIdx.x;
    if (tid < 32) {
        float s, c; sincosf(tid * (6.2831853071795864769f / 32.0f), &s, &c);
        tw[2 * tid] = c; tw[2 * tid + 1] = s;
    }
    __syncthreads();
    int bi = blockIdx.x;
    int s_ = bi >> 7, rest = bi & 127;
    int m1 = rest >> 2, dq = rest & 3;
    int d = dq * 8 + (tid >> 5), m2 = tid & 31;
    float ar = 0.f, ai = 0.f;
    #pragma unroll 8
    for (int j = 0; j < 32; j++) {
        int a = (j * d) & 31;
        float tr = tw[2 * a], ti = tw[2 * a + 1];
        int base = (((s_ * 32 + j) * 32 + m1) * 32 + m2) * 2;
        float cr = gKCP[base], ci = gKCP[base + 1];
        ar += tr * cr - ti * ci;
        ai += tr * ci + ti * cr;
    }
    int ob = (((s_ * 32 + d) * 32 + m1) * 32 + m2) * 2;
    gG[ob] = ar * 0.03125f; gG[ob + 1] = ai * 0.03125f;
}

// F1: Z[row][c] = sum_{w<128} (U|V)[row][w]*W1[w][c]
__global__ void __launch_bounds__(128) k_f1(const float* __restrict__ x) {
    extern __shared__ float sm[];
    float* Us = sm;                 // [128][65]
    float* Vs = sm + 128 * 65;
    float* Ws = sm + 2 * 128 * 65;  // [128][64]
    int tid = threadIdx.x;
    size_t r0 = (size_t)blockIdx.x * 128;
    for (int i = tid; i < 2048; i += 128)
        ((float4*)Ws)[i] = ((const float4*)gW1)[i];
    int ty = tid >> 2, tx = tid & 3;
    int lane = tid & 15, rg = tid >> 4;
    ull acc[4][8] = {};
    for (int kt = 0; kt < 2; kt++) {
        __syncthreads();
        #pragma unroll
        for (int rr = 0; rr < 16; rr++) {
            int row = rr * 8 + rg;
            const float* xp = x + (r0 + row) * 256 + kt * 64 + lane * 4;
            float4 a = *(const float4*)xp;
            float4 b = *(const float4*)(xp + 128);
            int o = row * 65 + lane * 4;
            Us[o] = a.x + b.x; Us[o + 1] = a.y + b.y; Us[o + 2] = a.z + b.z; Us[o + 3] = a.w + b.w;
            Vs[o] = a.x - b.x; Vs[o + 1] = a.y - b.y; Vs[o + 2] = a.z - b.z; Vs[o + 3] = a.w - b.w;
        }
        __syncthreads();
        const float* Ar = ((tx < 2) ? Us : Vs) + ty * 260;
        const float* Wk = Ws + tx * 16 + kt * 64 * 64;
        #pragma unroll 2
        for (int k = 0; k < 64; k++) {
            float a0 = Ar[k], a1 = Ar[65 + k], a2 = Ar[130 + k], a3 = Ar[195 + k];
            const ulonglong2* bw = (const ulonglong2*)(Wk + k * 64);
            ulonglong2 B0 = bw[0], B1 = bw[1], B2 = bw[2], B3 = bw[3];
            ull b[8] = {B0.x, B0.y, B1.x, B1.y, B2.x, B2.y, B3.x, B3.y};
            ull p0 = pk(a0), p1 = pk(a1), p2 = pk(a2), p3 = pk(a3);
            #pragma unroll
            for (int j = 0; j < 8; j++) {
                fma2(acc[0][j], p0, b[j]); fma2(acc[1][j], p1, b[j]);
                fma2(acc[2][j], p2, b[j]); fma2(acc[3][j], p3, b[j]);
            }
        }
    }
    #pragma unroll
    for (int i = 0; i < 4; i++) {
        float* o = &gZ[(r0 + ty * 4 + i) * 64 + tx * 16];
        #pragma unroll
        for (int q = 0; q < 4; q++) {
            float2 v0 = uf(acc[i][2 * q]), v1 = uf(acc[i][2 * q + 1]);
            *(float4*)&o[q * 4] = make_float4(v0.x, v0.y, v1.x, v1.y);
        }
    }
}

// F2: C/S GEMM over h + conjugate-pair reconstruction
__global__ void __launch_bounds__(160) k_f2() {
    __shared__ float Zs[64 * 68];
    __shared__ float Tbs[64 * 68];
    int tid = threadIdx.x;
    int img = blockIdx.x;
    int tx = tid & 7, ty = tid >> 3;  // ty valid < 17
    ull acc[4][4] = {};
    for (int hc = 0; hc < 4; hc++) {
        __syncthreads();
        for (int i = tid; i < 1024; i += 160) {
            int row = i >> 4, q = i & 15;
            *(float4*)&Zs[row * 68 + q * 4] =
                *(const float4*)&gZ[((size_t)img * 256 + hc * 64 + row) * 64 + q * 4];
        }
        for (int i = tid; i < 64 * 17; i += 160) {
            int row = i / 17, q = i % 17;
            *(float4*)&Tbs[row * 68 + q * 4] = *(const float4*)&gTb[(hc * 64 + row) * 68 + q * 4];
        }
        __syncthreads();
        if (ty < 17) {
            #pragma unroll 2
            for (int k = 0; k < 64; k++) {
                const float* at = &Tbs[k * 68 + ty * 4];
                float a0 = at[0], a1 = at[1], a2 = at[2], a3 = at[3];
                const ulonglong2* bw = (const ulonglong2*)&Zs[k * 68 + tx * 8];
                ulonglong2 B0 = bw[0], B1 = bw[1];
                ull b[4] = {B0.x, B0.y, B1.x, B1.y};
                ull p0 = pk(a0), p1 = pk(a1), p2 = pk(a2), p3 = pk(a3);
                #pragma unroll
                for (int j = 0; j < 4; j++) {
                    fma2(acc[0][j], p0, b[j]); fma2(acc[1][j], p1, b[j]);
                    fma2(acc[2][j], p2, b[j]); fma2(acc[3][j], p3, b[j]);
                }
            }
        }
    }
    if (ty < 17) {
        #pragma unroll
        for (int j = 0; j < 2; j++) {
            int t = 2 * ty + j;
            if (t > 32) break;
            float yp[8], ym[8];
            #pragma unroll
            for (int q = 0; q < 4; q++) {
                float2 C = uf(acc[2 * j][q]), S = uf(acc[2 * j + 1][q]);
                yp[2 * q]     = (C.x + S.y) * 0.00390625f;
                yp[2 * q + 1] = (C.y - S.x) * 0.00390625f;
                ym[2 * q]     = (C.x - S.y) * 0.00390625f;
                ym[2 * q + 1] = (C.y + S.x) * 0.00390625f;
            }
            if (t < 32) {
                float* o = &gY[((size_t)img * 64 + t) * 64 + tx * 8];
                *(float4*)o = *(float4*)&yp[0]; *(float4*)&o[4] = *(float4*)&yp[4];
            }
            if (t >= 1) {
                float* o = &gY[((size_t)img * 64 + (64 - t)) * 64 + tx * 8];
                *(float4*)o = *(float4*)&ym[0]; *(float4*)&o[4] = *(float4*)&ym[4];
            }
        }
    }
}

__global__ void k_mix() {
    __shared__ float Ys[8][32][16];
    __shared__ float Gr[32][9], Gi[32][9];
    int tid = threadIdx.x;
    int bi = blockIdx.x;
    int k1i = bi >> 2, q = bi & 3;
    int s_ = (k1i < 32) ? 0 : 1;
    int m1 = k1i & 31;
    int b = tid >> 5, c = tid & 31;
    {
        const float4* ysrc = (const float4*)(gY + ((size_t)(b * 32 + c) * 64 + k1i) * 64 + q * 16);
        float4* dst = (float4*)&Ys[b][c][0];
        #pragma unroll
        for (int t = 0; t < 4; t++) dst[t] = ysrc[t];
    }
    {
        int d = tid >> 3, kq = tid & 7;
        int m2 = k2map(q * 8 + kq);
        int gi = (((s_ * 32 + d) * 32 + m1) * 32 + m2) * 2;
        Gr[d][kq] = gG[gi]; Gi[d][kq] = gG[gi + 1];
    }
    __syncthreads();
    float ar[8] = {}, ai[8] = {};
    for (int cc = 0; cc < 32; cc++) {
        int d = (c - cc) & 31;
        #pragma unroll
        for (int kq = 0; kq < 8; kq++) {
            float gr = Gr[d][kq], gim = Gi[d][kq];
            float yr = Ys[b][cc][2 * kq], yi = Ys[b][cc][2 * kq + 1];
            ar[kq] += gr * yr - gim * yi;
            ai[kq] += gr * yi + gim * yr;
        }
    }
    float* fo = gF + ((size_t)(b * 32 + c) * 64 + k1i) * 64 + q * 16;
    #pragma unroll
    for (int kq = 0; kq < 8; kq++) { fo[2 * kq] = ar[kq]; fo[2 * kq + 1] = ai[kq]; }
}

// I1: T[h][c] = sum_t cos(th)/16 * P[t][c] + sin(th)/16 * Q[t][c]
__global__ void __launch_bounds__(256) k_i1() {
    extern __shared__ float sm[];
    float* At = sm;             // [256][69]
    float* Bp = sm + 256 * 69;  // [66][68]
    int tid = threadIdx.x;
    int img = blockIdx.x;
    int tx = tid & 3, ty = (tid >> 2) & 15, hc = tid >> 6;
    for (int i = tid; i < 256 * 69; i += 256) At[i] = gTA[i];
    for (int i = tid; i < 33 * 16; i += 256) {
        int t = i >> 4, q = i & 15;
        float4 fp = make_float4(0, 0, 0, 0), fm = make_float4(0, 0, 0, 0);
        if (t <= 31) fp = *(const float4*)&gF[((size_t)img * 64 + t) * 64 + q * 4];
        if (t >= 1)  fm = *(const float4*)&gF[((size_t)img * 64 + (64 - t)) * 64 + q * 4];
        float4 P = make_float4(fp.x + fm.x, fp.y + fm.y, fp.z + fm.z, fp.w + fm.w);
        float4 d = make_float4(fp.x - fm.x, fp.y - fm.y, fp.z - fm.z, fp.w - fm.w);
        *(float4*)&Bp[(2 * t) * 68 + q * 4]     = P;
        *(float4*)&Bp[(2 * t + 1) * 68 + q * 4] = make_float4(-d.y, d.x, -d.w, d.z);
    }
    __syncthreads();
    ull acc[4][8] = {};
    int hbase = hc * 64 + ty * 4;
    #pragma unroll 2
    for (int k = 0; k < 66; k++) {
        float a0 = At[(hbase + 0) * 69 + k], a1 = At[(hbase + 1) * 69 + k];
        float a2 = At[(hbase + 2) * 69 + k], a3 = At[(hbase + 3) * 69 + k];
        const ulonglong2* bw = (const ulonglong2*)&Bp[k * 68 + tx * 16];
        ulonglong2 B0 = bw[0], B1 = bw[1], B2 = bw[2], B3 = bw[3];
        ull b[8] = {B0.x, B0.y, B1.x, B1.y, B2.x, B2.y, B3.x, B3.y};
        ull p0 = pk(a0), p1 = pk(a1), p2 = pk(a2), p3 = pk(a3);
        #pragma unroll
        for (int j = 0; j < 8; j++) {
            fma2(acc[0][j], p0, b[j]); fma2(acc[1][j], p1, b[j]);
            fma2(acc[2][j], p2, b[j]); fma2(acc[3][j], p3, b[j]);
        }
    }
    #pragma unroll
    for (int i = 0; i < 4; i++) {
        float* o = &gT[((size_t)img * 256 + hbase + i) * 64 + tx * 16];
        #pragma unroll
        for (int q = 0; q < 4; q++) {
            float2 v0 = uf(acc[i][2 * q]), v1 = uf(acc[i][2 * q + 1]);
            *(float4*)&o[q * 4] = make_float4(v0.x, v0.y, v1.x, v1.y);
        }
    }
}

// I2: y[h][w], y[h][w+128] from parity-split accumulators
__global__ void __launch_bounds__(256) k_i2(float* __restrict__ out) {
    extern __shared__ float sm[];
    float* Ts = sm;             // [128][65]
    float* Wb = sm + 128 * 65;  // [64][64]
    int tid = threadIdx.x;
    int bi = blockIdx.x;        // 1024
    size_t r0 = (size_t)(bi >> 1) * 128;
    int w0 = (bi & 1) * 64;
    {
        int lane = tid & 15, rg = tid >> 4;
        #pragma unroll
        for (int rr = 0; rr < 8; rr++) {
            int row = rr * 16 + rg;
            float4 v = *(const float4*)&gT[(r0 + row) * 64 + lane * 4];
            int o = row * 65 + lane * 4;
            Ts[o] = v.x; Ts[o + 1] = v.y; Ts[o + 2] = v.z; Ts[o + 3] = v.w;
        }
        for (int i = tid; i < 1024; i += 256) {
            int row = i >> 4, q = i & 15;
            *(float4*)&Wb[row * 64 + q * 4] = *(const float4*)&gWB2[row * 128 + w0 + q * 4];
        }
    }
    __syncthreads();
    int tx = tid & 7, ty = tid >> 3;
    ull accA[4][4] = {}, accB[4][4] = {};
    const float* Ar = Ts + ty * 260;
    #pragma unroll 2
    for (int k = 0; k < 32; k++) {
        float a0 = Ar[k], a1 = Ar[65 + k], a2 = Ar[130 + k], a3 = Ar[195 + k];
        const ulonglong2* bw = (const ulonglong2*)&Wb[k * 64 + tx * 8];
        ulonglong2 B0 = bw[0], B1 = bw[1];
        ull b[4] = {B0.x, B0.y, B1.x, B1.y};
        ull p0 = pk(a0), p1 = pk(a1), p2 = pk(a2), p3 = pk(a3);
        #pragma unroll
        for (int j = 0; j < 4; j++) {
            fma2(accA[0][j], p0, b[j]); fma2(accA[1][j], p1, b[j]);
            fma2(accA[2][j], p2, b[j]); fma2(accA[3][j], p3, b[j]);
        }
    }
    #pragma unroll 2
    for (int k = 32; k < 64; k++) {
        float a0 = Ar[k], a1 = Ar[65 + k], a2 = Ar[130 + k], a3 = Ar[195 + k];
        const ulonglong2* bw = (const ulonglong2*)&Wb[k * 64 + tx * 8];
        ulonglong2 B0 = bw[0], B1 = bw[1];
        ull b[4] = {B0.x, B0.y, B1.x, B1.y};
        ull p0 = pk(a0), p1 = pk(a1), p2 = pk(a2), p3 = pk(a3);
        #pragma unroll
        for (int j = 0; j < 4; j++) {
            fma2(accB[0][j], p0, b[j]); fma2(accB[1][j], p1, b[j]);
            fma2(accB[2][j], p2, b[j]); fma2(accB[3][j], p3, b[j]);
        }
    }
    #pragma unroll
    for (int i = 0; i < 4; i++) {
        float s[8], d8[8];
        #pragma unroll
        for (int q = 0; q < 4; q++) {
            float2 a = uf(accA[i][q]), b = uf(accB[i][q]);
            s[2 * q] = a.x + b.x;  s[2 * q + 1] = a.y + b.y;
            d8[2 * q] = a.x - b.x; d8[2 * q + 1] = a.y - b.y;
        }
        float* o = out + (r0 + ty * 4 + i) * 256 + w0 + tx * 8;
        *(float4*)o = *(float4*)&s[0]; *(float4*)(o + 4) = *(float4*)&s[4];
        *(float4*)(o + 128) = *(float4*)&d8[0]; *(float4*)(o + 132) = *(float4*)&d8[4];
    }
}

extern "C" void kernel_launch(void* const* d_in, const int* in_sizes, int n_in,
                              void* d_out, int out_size) {
    const float* x    = (const float*)d_in[0];
    const float* kern = (const float*)d_in[1];
    const float* r    = (const float*)d_in[2];
    float* out = (float*)d_out;

    cudaFuncSetAttribute(k_f1, cudaFuncAttributeMaxDynamicSharedMemorySize, 99328);
    cudaFuncSetAttribute(k_i1, cudaFuncAttributeMaxDynamicSharedMemorySize, 88608);
    cudaFuncSetAttribute(k_i2, cudaFuncAttributeMaxDynamicSharedMemorySize, 49664);

    k_tables<<<69, 256>>>();
    k_pow<<<256, 256>>>(kern, r);
    k_g<<<256, 256>>>();
    k_f1<<<512, 128, 99328>>>(x);
    k_f2<<<256, 160>>>();
    k_mix<<<256, 256>>>();
    k_i1<<<256, 256, 88608>>>();
    k_i2<<<1024, 256, 49664>>>(out);
}